// round 15
// baseline (speedup 1.0000x reference)
#include <cuda_runtime.h>
#include <math.h>
#include <stdint.h>

// Problem constants
constexpr int Bb  = 8;
constexpr int Tt  = 256;
constexpr int Ee  = 768;
constexpr int Nn  = 1024;
constexpr int Vv  = 32000;
constexpr int BT  = Bb * Tt;   // 2048
constexpr int TCH = 64;        // timesteps per chunk
constexpr int RCH = TCH * Bb;  // 512 rows per chunk (t-major)

// ---------------- device scratch ----------------
__device__ float g_X [BT * Nn];
__device__ float g_S [2][Bb * Nn];
__device__ float g_H [BT * Nn];          // t-major: row = t*Bb + b
__device__ float g_Hn[BT * Nn];          // t-major
__device__ float g_P [BT * Ee];          // t-major, tf32-rounded
__device__ float g_Bt[(size_t)Vv * Ee];  // w_head^T [V][E], tf32-rounded
__device__ unsigned g_count;
__device__ volatile unsigned g_gen;      // scan generation: 1 + substeps done
__device__ unsigned g_wcount;
__device__ volatile unsigned g_wgen;     // worker stage barrier

__global__ void init_barrier_kernel() {
    g_count = 0u; g_gen = 0u;
    g_wcount = 0u; g_wgen = 0u;
}

// ---------------- helpers ----------------
__device__ __forceinline__ uint32_t smem_u32(const void* p) {
    uint32_t a;
    asm("{ .reg .u64 t; cvta.to.shared.u64 t, %1; cvt.u32.u64 %0, t; }" : "=r"(a) : "l"(p));
    return a;
}
__device__ __forceinline__ void cp16(uint32_t dst, const void* src) {
    asm volatile("cp.async.cg.shared.global [%0], [%1], 16;" :: "r"(dst), "l"(src));
}
__device__ __forceinline__ void cp_commit() {
    asm volatile("cp.async.commit_group;" ::: "memory");
}
template<int N>
__device__ __forceinline__ void cp_wait() {
    asm volatile("cp.async.wait_group %0;" :: "n"(N) : "memory");
}
__device__ __forceinline__ float tf32r(float x) {
    uint32_t r;
    asm("cvt.rna.tf32.f32 %0, %1;" : "=r"(r) : "f"(x));
    return __uint_as_float(r);
}
__device__ __forceinline__ uint32_t ldsf(const float* p) {
    return *(const uint32_t*)p;
}
__device__ __forceinline__ void mma_tf32(float* c, const uint32_t* a,
                                         uint32_t b0, uint32_t b1) {
    asm volatile(
        "mma.sync.aligned.m16n8k8.row.col.f32.tf32.tf32.f32 "
        "{%0,%1,%2,%3}, {%4,%5,%6,%7}, {%8,%9}, {%0,%1,%2,%3};"
        : "+f"(c[0]), "+f"(c[1]), "+f"(c[2]), "+f"(c[3])
        : "r"(a[0]), "r"(a[1]), "r"(a[2]), "r"(a[3]), "r"(b0), "r"(b1));
}
__device__ __forceinline__ void bar_scan() {   // threads 0-127
    asm volatile("bar.sync 1, 128;" ::: "memory");
}
__device__ __forceinline__ void bar_work() {   // threads 128-383
    asm volatile("bar.sync 2, 256;" ::: "memory");
}

// ---------------- fused persistent kernel ----------------
constexpr int RNCTA = 128;
constexpr int FTPB  = 384;   // 128 scan + 256 worker threads

// head tile constants
constexpr int HSTRf   = 36;
constexpr int HTILEf  = 128 * HSTRf * 4;   // 18432 B
constexpr int HSTAGEf = HTILEf * 2;        // 36864 B
constexpr int HG_SMEM = HSTAGEf * 2;       // 73728 B dynamic worker smem

__global__ void __launch_bounds__(FTPB, 1) fused_kernel(
    const float* __restrict__ w_bb, const float* __restrict__ b_bb,
    const float* __restrict__ gamma, const float* __restrict__ beta,
    const float* __restrict__ w_out, const float* __restrict__ w_head,
    float* __restrict__ out)
{
    __shared__ float sV[Bb * Nn];          // 32 KB (scan)
    __shared__ float sRed[4][16][33];      // 8.4 KB (scan)
    __shared__ float sLn[2][8];            // ln scratch (workers)
    extern __shared__ char wsm[];          // 73728 B (workers)

    const int tid = threadIdx.x;
    const int bid = blockIdx.x;

    if (tid < 128) {
        // ======================= SCAN (R9 logic, named barriers) =======================
        const int lane  = tid & 31;
        const int warp  = tid >> 5;
        const int jbase = bid * 8;
        const int j0    = jbase + warp * 2;

        float wreg[8][4][2];
#pragma unroll
        for (int i = 0; i < 8; i++) {
#pragma unroll
            for (int d = 0; d < 4; d++) {
                int k = 4 * lane + 128 * i + d;
                wreg[i][d][0] = w_bb[k * Nn + j0];
                wreg[i][d][1] = w_bb[k * Nn + j0 + 1];
            }
        }
        const float bias0 = b_bb[j0];
        const float bias1 = b_bb[j0 + 1];
        const uint32_t sV32 = smem_u32(sV);

        if (tid < 64) {
            int b = tid >> 3, c = tid & 7;
            g_S[0][b * Nn + jbase + c] = 0.f;
        }
        // grid barrier (scan threads only)
        bar_scan();
        if (tid == 0) {
            unsigned my = g_gen;
            __threadfence();
            if (atomicAdd(&g_count, 1u) == RNCTA - 1) {
                g_count = 0u; __threadfence(); g_gen = my + 1u;
            } else { while (g_gen == my) { } }
        }
        bar_scan();

        int cur = 0;
#pragma unroll 1
        for (int t = 0; t < Tt; t++) {
#pragma unroll 1
            for (int step = 0; step < 4; step++) {
                const float4* src = (const float4*)&g_S[cur][0];
                float acc[16];
#pragma unroll
                for (int o = 0; o < 16; o++) acc[o] = 0.f;

                if (step == 0) {
                    const float4* xs = (const float4*)g_X;
                    for (int r = tid; r < (Bb * Nn) / 4; r += 128) {
                        float4 a = __ldcg(src + r);
                        int b  = r >> 8;
                        int k4 = r & 255;
                        float4 x = xs[(b * Tt + t) * (Nn / 4) + k4];
                        a.x += x.x; a.y += x.y; a.z += x.z; a.w += x.w;
                        ((float4*)sV)[r] = a;
                    }
                    bar_scan();
#pragma unroll
                    for (int i = 0; i < 8; i++) {
#pragma unroll
                        for (int b = 0; b < Bb; b++) {
                            float4 v = *(const float4*)&sV[b * Nn + 4 * lane + 128 * i];
                            acc[b*2+0] = fmaf(v.x, wreg[i][0][0], acc[b*2+0]);
                            acc[b*2+0] = fmaf(v.y, wreg[i][1][0], acc[b*2+0]);
                            acc[b*2+0] = fmaf(v.z, wreg[i][2][0], acc[b*2+0]);
                            acc[b*2+0] = fmaf(v.w, wreg[i][3][0], acc[b*2+0]);
                            acc[b*2+1] = fmaf(v.x, wreg[i][0][1], acc[b*2+1]);
                            acc[b*2+1] = fmaf(v.y, wreg[i][1][1], acc[b*2+1]);
                            acc[b*2+1] = fmaf(v.z, wreg[i][2][1], acc[b*2+1]);
                            acc[b*2+1] = fmaf(v.w, wreg[i][3][1], acc[b*2+1]);
                        }
                    }
                } else {
#pragma unroll
                    for (int k = 0; k < 8; k++) {
                        int r = tid + k * 128;
                        cp16(sV32 + r * 16, src + r);
                    }
                    cp_commit();
#pragma unroll
                    for (int k = 8; k < 16; k++) {
                        int r = tid + k * 128;
                        cp16(sV32 + r * 16, src + r);
                    }
                    cp_commit();

                    cp_wait<1>();
                    bar_scan();
#pragma unroll
                    for (int i = 0; i < 8; i++) {
#pragma unroll
                        for (int b = 0; b < 4; b++) {
                            float4 v = *(const float4*)&sV[b * Nn + 4 * lane + 128 * i];
                            acc[b*2+0] = fmaf(v.x, wreg[i][0][0], acc[b*2+0]);
                            acc[b*2+0] = fmaf(v.y, wreg[i][1][0], acc[b*2+0]);
                            acc[b*2+0] = fmaf(v.z, wreg[i][2][0], acc[b*2+0]);
                            acc[b*2+0] = fmaf(v.w, wreg[i][3][0], acc[b*2+0]);
                            acc[b*2+1] = fmaf(v.x, wreg[i][0][1], acc[b*2+1]);
                            acc[b*2+1] = fmaf(v.y, wreg[i][1][1], acc[b*2+1]);
                            acc[b*2+1] = fmaf(v.z, wreg[i][2][1], acc[b*2+1]);
                            acc[b*2+1] = fmaf(v.w, wreg[i][3][1], acc[b*2+1]);
                        }
                    }
                    cp_wait<0>();
                    bar_scan();
#pragma unroll
                    for (int i = 0; i < 8; i++) {
#pragma unroll
                        for (int b = 4; b < 8; b++) {
                            float4 v = *(const float4*)&sV[b * Nn + 4 * lane + 128 * i];
                            acc[b*2+0] = fmaf(v.x, wreg[i][0][0], acc[b*2+0]);
                            acc[b*2+0] = fmaf(v.y, wreg[i][1][0], acc[b*2+0]);
                            acc[b*2+0] = fmaf(v.z, wreg[i][2][0], acc[b*2+0]);
                            acc[b*2+0] = fmaf(v.w, wreg[i][3][0], acc[b*2+0]);
                            acc[b*2+1] = fmaf(v.x, wreg[i][0][1], acc[b*2+1]);
                            acc[b*2+1] = fmaf(v.y, wreg[i][1][1], acc[b*2+1]);
                            acc[b*2+1] = fmaf(v.z, wreg[i][2][1], acc[b*2+1]);
                            acc[b*2+1] = fmaf(v.w, wreg[i][3][1], acc[b*2+1]);
                        }
                    }
                }

#pragma unroll
                for (int o = 0; o < 16; o++) sRed[warp][o][lane] = acc[o];
                __syncwarp();

                const int nxt = cur ^ 1;
                {
                    const int o = lane >> 1;
                    const int h = lane & 1;
                    float s = 0.f;
#pragma unroll
                    for (int l = 0; l < 16; l++) s += sRed[warp][o][h * 16 + l];
                    s += __shfl_xor_sync(0xffffffffu, s, 1);
                    if (h == 0) {
                        int b = o >> 1, j = o & 1;
                        s += (j ? bias1 : bias0);
                        float sn = tanhf(s);
                        g_S[nxt][b * Nn + j0 + j] = sn;
                        if (step == 3) g_H[(t * Bb + b) * Nn + j0 + j] = sn;  // t-major
                    }
                }
                cur ^= 1;

                bar_scan();
                if (tid == 0) {
                    unsigned my = g_gen;
                    __threadfence();
                    if (atomicAdd(&g_count, 1u) == RNCTA - 1) {
                        g_count = 0u; __threadfence(); g_gen = my + 1u;
                    } else { while (g_gen == my) { } }
                }
                bar_scan();
            }
        }
    } else {
        // ======================= EPILOGUE WORKERS (256 threads) =======================
        const int wtid = tid - 128;
        const int lane = wtid & 31;
        const int warp = wtid >> 5;     // 0..7

        // --- Stage -1: transpose + tf32-round w_head into g_Bt (scan-chunk-0 idle time)
        {
            float (*tile)[33] = (float(*)[33])wsm;
            const int tx  = wtid & 31;
            const int ty8 = wtid >> 5;   // 0..7
#pragma unroll 1
            for (int ti = bid; ti < 24000; ti += RNCTA) {
                int n0 = (ti % 1000) * 32;
                int k0 = (ti / 1000) * 32;
#pragma unroll
                for (int j = 0; j < 32; j += 8)
                    tile[ty8 + j][tx] = w_head[(size_t)(k0 + ty8 + j) * Vv + n0 + tx];
                bar_work();
#pragma unroll
                for (int j = 0; j < 32; j += 8)
                    g_Bt[(size_t)(n0 + ty8 + j) * Ee + k0 + tx] = tf32r(tile[tx][ty8 + j]);
                bar_work();
            }
        }

#pragma unroll 1
        for (int c = 0; c < 4; c++) {
            // --- wait for scan chunk c (g_gen = 1 + substeps completed)
            if (tid == 128) {
                unsigned thr = 1u + 256u * (unsigned)(c + 1);
                while (g_gen < thr) { }
            }
            bar_work();

            // --- Stage 1: layernorm for this CTA's 4 rows of the chunk
#pragma unroll 1
            for (int rr = 0; rr < 4; rr++) {
                int row = c * RCH + bid * 4 + rr;
                float4 v = __ldcg((const float4*)(g_H + (size_t)row * Nn) + wtid);
                float s = v.x + v.y + v.z + v.w;
                float q = v.x*v.x + v.y*v.y + v.z*v.z + v.w*v.w;
#pragma unroll
                for (int off = 16; off; off >>= 1) {
                    s += __shfl_xor_sync(0xffffffffu, s, off);
                    q += __shfl_xor_sync(0xffffffffu, q, off);
                }
                if (lane == 0) { sLn[0][warp] = s; sLn[1][warp] = q; }
                bar_work();
                float ts = 0.f, tq = 0.f;
#pragma unroll
                for (int i = 0; i < 8; i++) { ts += sLn[0][i]; tq += sLn[1][i]; }
                float m   = ts * (1.f / Nn);
                float var = tq * (1.f / Nn) - m * m;
                float r   = rsqrtf(var + 1e-5f);
                float4 g  = ((const float4*)gamma)[wtid];
                float4 be = ((const float4*)beta)[wtid];
                float4 o;
                o.x = (v.x - m) * r * g.x + be.x;
                o.y = (v.y - m) * r * g.y + be.y;
                o.z = (v.z - m) * r * g.z + be.z;
                o.w = (v.w - m) * r * g.w + be.w;
                ((float4*)(g_Hn + (size_t)row * Nn))[wtid] = o;
                bar_work();
            }

            // --- worker grid barrier: all ln done
            bar_work();
            if (tid == 128) {
                unsigned my = g_wgen;
                __threadfence();
                if (atomicAdd(&g_wcount, 1u) == RNCTA - 1) {
                    g_wcount = 0u; __threadfence(); g_wgen = my + 1u;
                } else { while (g_wgen == my) { } }
            }
            bar_work();

            // --- Stage 2: P_chunk = Hn_chunk @ w_out (tf32-rounded), 24 tiles, bid<24
            if (bid < 24) {
                float* As = (float*)wsm;          // [8][128]
                float* Bs = As + 8 * 128;         // [8][128]
                const int mt = bid / 6, nt = bid % 6;
                const int bm = c * RCH + mt * 128;
                const int bn = nt * 128;
                const int innerRowA = wtid >> 1;
                const int innerColA = (wtid & 1) * 4;
                const int innerRowB = wtid >> 5;
                const int innerColB = (wtid & 31) * 4;
                const int tr = wtid >> 4;
                const int tc = wtid & 15;
                const size_t arowBase = (size_t)(bm + innerRowA) * Nn;

                float acc[8][8];
#pragma unroll
                for (int i = 0; i < 8; i++)
#pragma unroll
                    for (int j = 0; j < 8; j++) acc[i][j] = 0.f;

#pragma unroll 1
                for (int kb = 0; kb < Nn; kb += 8) {
                    float4 a = __ldcg((const float4*)(g_Hn + arowBase + kb + innerColA));
                    float4 b = *(const float4*)(w_out + (kb + innerRowB) * Ee + bn + innerColB);
                    As[(innerColA + 0) * 128 + innerRowA] = a.x;
                    As[(innerColA + 1) * 128 + innerRowA] = a.y;
                    As[(innerColA + 2) * 128 + innerRowA] = a.z;
                    As[(innerColA + 3) * 128 + innerRowA] = a.w;
                    *(float4*)&Bs[innerRowB * 128 + innerColB] = b;
                    bar_work();
#pragma unroll
                    for (int k = 0; k < 8; k++) {
                        float rm[8], rn[8];
#pragma unroll
                        for (int i = 0; i < 8; i++) rm[i] = As[k * 128 + tr * 8 + i];
#pragma unroll
                        for (int j = 0; j < 8; j++) rn[j] = Bs[k * 128 + tc * 8 + j];
#pragma unroll
                        for (int i = 0; i < 8; i++)
#pragma unroll
                            for (int j = 0; j < 8; j++)
                                acc[i][j] = fmaf(rm[i], rn[j], acc[i][j]);
                    }
                    bar_work();
                }
#pragma unroll
                for (int i = 0; i < 8; i++) {
                    size_t crow = (size_t)(bm + tr * 8 + i) * Ee + bn + tc * 8;
#pragma unroll
                    for (int j4 = 0; j4 < 2; j4++) {
                        float4 v;
                        v.x = tf32r(acc[i][j4*4+0]); v.y = tf32r(acc[i][j4*4+1]);
                        v.z = tf32r(acc[i][j4*4+2]); v.w = tf32r(acc[i][j4*4+3]);
                        *(float4*)(g_P + crow + j4 * 4) = v;
                    }
                }
            }

            // --- worker grid barrier: P chunk ready (also guards Bt after chunk 0)
            bar_work();
            if (tid == 128) {
                unsigned my = g_wgen;
                __threadfence();
                if (atomicAdd(&g_wcount, 1u) == RNCTA - 1) {
                    g_wcount = 0u; __threadfence(); g_wgen = my + 1u;
                } else { while (g_wgen == my) { } }
            }
            bar_work();

            // --- Stage 3: head GEMM for this chunk: 4 x 250 = 1000 tiles
            const uint32_t sbase = smem_u32(wsm);
#pragma unroll 1
            for (int ti = bid; ti < 1000; ti += RNCTA) {
                const int mt = ti / 250, nt = ti % 250;
                const int m0 = c * RCH + mt * 128;
                const int n0 = nt * 128;
                const int wm = (warp >> 1) * 32;
                const int wn = (warp & 1) * 64;
                const int gq = lane >> 2;
                const int tq = lane & 3;

                const int lr = wtid >> 1;
                const int lc = (wtid & 1) * 16;
                const uint32_t soff = (uint32_t)(lr * HSTRf + lc) * 4;
                const float* gA = g_P  + (size_t)(m0 + lr) * Ee + lc;
                const float* gB = g_Bt + (size_t)(n0 + lr) * Ee + lc;

                float cc[2][8][4];
#pragma unroll
                for (int i = 0; i < 2; i++)
#pragma unroll
                    for (int j = 0; j < 8; j++)
#pragma unroll
                        for (int q = 0; q < 4; q++) cc[i][j][q] = 0.f;

                {
                    uint32_t dA = sbase + soff;
                    uint32_t dB = sbase + HTILEf + soff;
#pragma unroll
                    for (int q = 0; q < 4; q++) {
                        cp16(dA + q * 16, gA + q * 4);
                        cp16(dB + q * 16, gB + q * 4);
                    }
                    cp_commit();
                }

#pragma unroll 1
                for (int it = 0; it < 24; it++) {
                    if (it + 1 < 24) {
                        const int st = (it + 1) & 1;
                        const int kb = (it + 1) * 32;
                        uint32_t dA = sbase + st * HSTAGEf + soff;
                        uint32_t dB = sbase + st * HSTAGEf + HTILEf + soff;
#pragma unroll
                        for (int q = 0; q < 4; q++) {
                            cp16(dA + q * 16, gA + kb + q * 4);
                            cp16(dB + q * 16, gB + kb + q * 4);
                        }
                        cp_commit();
                        cp_wait<1>();
                    } else {
                        cp_wait<0>();
                    }
                    bar_work();

                    const float* sA = (const float*)(wsm + (it & 1) * HSTAGEf);
                    const float* sB = (const float*)(wsm + (it & 1) * HSTAGEf + HTILEf);

#pragma unroll
                    for (int ks = 0; ks < 4; ks++) {
                        const int k0 = ks * 8;
                        uint32_t a[2][4];
#pragma unroll
                        for (int i = 0; i < 2; i++) {
                            const float* r0 = &sA[(wm + 16 * i + gq) * HSTRf + k0 + tq];
                            const float* r1 = &sA[(wm + 16 * i + gq + 8) * HSTRf + k0 + tq];
                            a[i][0] = ldsf(r0);
                            a[i][1] = ldsf(r1);
                            a[i][2] = ldsf(r0 + 4);
                            a[i][3] = ldsf(r1 + 4);
                        }
#pragma unroll
                        for (int j = 0; j < 8; j++) {
                            const float* nb = &sB[(wn + 8 * j + gq) * HSTRf + k0 + tq];
                            uint32_t b0 = ldsf(nb);
                            uint32_t b1 = ldsf(nb + 4);
                            mma_tf32(cc[0][j], a[0], b0, b1);
                            mma_tf32(cc[1][j], a[1], b0, b1);
                        }
                    }
                    bar_work();
                }

                // epilogue: remap t-major row -> output row (b*Tt + t)
#pragma unroll
                for (int i = 0; i < 2; i++) {
#pragma unroll
                    for (int j = 0; j < 8; j++) {
                        int gr0 = m0 + wm + 16 * i + gq;
                        int gr1 = gr0 + 8;
                        int or0 = (gr0 & 7) * Tt + (gr0 >> 3);
                        int or1 = (gr1 & 7) * Tt + (gr1 >> 3);
                        int col = n0 + wn + 8 * j + 2 * tq;
                        float2 v0 = make_float2(cc[i][j][0], cc[i][j][1]);
                        float2 v1 = make_float2(cc[i][j][2], cc[i][j][3]);
                        *(float2*)(out + (size_t)or0 * Vv + col) = v0;
                        *(float2*)(out + (size_t)or1 * Vv + col) = v1;
                    }
                }
            }
        }
    }
}

// ---------------- prologue GEMM: X = emb[ids] @ w_in + b_in ----------------
__global__ void __launch_bounds__(256) sgemmA_kernel(
    const float* __restrict__ A, const float* __restrict__ Bm, float* __restrict__ C,
    const int* __restrict__ ids, const float* __restrict__ bias)
{
    constexpr int BM = 128, BN = 128, BK = 8;
    constexpr int M = BT, N = Nn, K = Ee;
    __shared__ float As[BK][BM];
    __shared__ float Bs[BK][BN];

    const int tid = threadIdx.x;
    const int bm  = blockIdx.y * BM;
    const int bn  = blockIdx.x * BN;

    const int innerRowA = tid >> 1;
    const int innerColA = (tid & 1) * 4;
    const int innerRowB = tid >> 5;
    const int innerColB = (tid & 31) * 4;
    const int tr = tid >> 4;
    const int tc = tid & 15;

    const int arow = bm + innerRowA;
    const int arowBase = ids[arow] * K;

    float acc[8][8];
#pragma unroll
    for (int i = 0; i < 8; i++)
#pragma unroll
        for (int j = 0; j < 8; j++) acc[i][j] = 0.f;

    for (int kb = 0; kb < K; kb += BK) {
        float4 a = *(const float4*)(A + arowBase + kb + innerColA);
        float4 b = *(const float4*)(Bm + (kb + innerRowB) * N + bn + innerColB);
        As[innerColA + 0][innerRowA] = a.x;
        As[innerColA + 1][innerRowA] = a.y;
        As[innerColA + 2][innerRowA] = a.z;
        As[innerColA + 3][innerRowA] = a.w;
        *(float4*)&Bs[innerRowB][innerColB] = b;
        __syncthreads();

#pragma unroll
        for (int k = 0; k < BK; k++) {
            float rm[8], rn[8];
#pragma unroll
            for (int i = 0; i < 8; i++) rm[i] = As[k][tr * 8 + i];
#pragma unroll
            for (int j = 0; j < 8; j++) rn[j] = Bs[k][tc * 8 + j];
#pragma unroll
            for (int i = 0; i < 8; i++)
#pragma unroll
                for (int j = 0; j < 8; j++)
                    acc[i][j] = fmaf(rm[i], rn[j], acc[i][j]);
        }
        __syncthreads();
    }

#pragma unroll
    for (int i = 0; i < 8; i++) {
        int crow = (bm + tr * 8 + i) * N + bn + tc * 8;
#pragma unroll
        for (int j4 = 0; j4 < 2; j4++) {
            float4 v;
            v.x = acc[i][j4*4+0]; v.y = acc[i][j4*4+1];
            v.z = acc[i][j4*4+2]; v.w = acc[i][j4*4+3];
            float4 bb = *(const float4*)(bias + bn + tc * 8 + j4 * 4);
            v.x += bb.x; v.y += bb.y; v.z += bb.z; v.w += bb.w;
            *(float4*)(C + crow + j4 * 4) = v;
        }
    }
}

// ---------------- launch ----------------
extern "C" void kernel_launch(void* const* d_in, const int* in_sizes, int n_in,
                              void* d_out, int out_size)
{
    const int*   ids    = (const int*)  d_in[0];
    const float* emb    = (const float*)d_in[1];
    const float* w_in   = (const float*)d_in[2];
    const float* b_in   = (const float*)d_in[3];
    const float* w_bb   = (const float*)d_in[4];
    const float* b_bb   = (const float*)d_in[5];
    const float* gamma  = (const float*)d_in[6];
    const float* beta   = (const float*)d_in[7];
    const float* w_out  = (const float*)d_in[8];
    const float* w_head = (const float*)d_in[9];
    float* out = (float*)d_out;

    float* pX = nullptr;
    cudaGetSymbolAddress((void**)&pX, g_X);

    cudaFuncSetAttribute(fused_kernel,
                         cudaFuncAttributeMaxDynamicSharedMemorySize, HG_SMEM);

    // 0. reset barrier state (device globals persist across graph replays)
    init_barrier_kernel<<<1, 1>>>();

    // 1. X = emb[ids] @ w_in + b_in
    {
        dim3 g(Nn / 128, BT / 128);
        sgemmA_kernel<<<g, 256>>>(emb, w_in, pX, ids, b_in);
    }

    // 2. fused scan + warp-specialized epilogue pipeline (writes out directly)
    fused_kernel<<<RNCTA, FTPB, HG_SMEM>>>(w_bb, b_bb, gamma, beta, w_out, w_head, out);
}

// round 16
// speedup vs baseline: 1.0436x; 1.0436x over previous
#include <cuda_runtime.h>
#include <math.h>
#include <stdint.h>

// Problem constants
constexpr int Bb  = 8;
constexpr int Tt  = 256;
constexpr int Ee  = 768;
constexpr int Nn  = 1024;
constexpr int Vv  = 32000;
constexpr int BT  = Bb * Tt;   // 2048
constexpr int TCH = 64;        // timesteps per chunk
constexpr int RCH = TCH * Bb;  // 512 rows per chunk (t-major)

// ---------------- device scratch ----------------
__device__ float g_X [BT * Nn];
__device__ float g_S [2][Bb * Nn];
__device__ float g_H [BT * Nn];          // t-major: row = t*Bb + b
__device__ float g_Hn[BT * Nn];          // t-major
__device__ float g_P [BT * Ee];          // t-major, tf32-rounded
__device__ float g_Bt[(size_t)Vv * Ee];  // w_head^T [V][E], tf32-rounded
__device__ unsigned g_count;
__device__ volatile unsigned g_gen;      // scan generation: 1 + substeps done
__device__ unsigned g_wcount;
__device__ volatile unsigned g_wgen;     // worker stage barrier

__global__ void init_barrier_kernel() {
    g_count = 0u; g_gen = 0u;
    g_wcount = 0u; g_wgen = 0u;
}

// ---------------- helpers ----------------
__device__ __forceinline__ uint32_t smem_u32(const void* p) {
    uint32_t a;
    asm("{ .reg .u64 t; cvta.to.shared.u64 t, %1; cvt.u32.u64 %0, t; }" : "=r"(a) : "l"(p));
    return a;
}
__device__ __forceinline__ void cp16(uint32_t dst, const void* src) {
    asm volatile("cp.async.cg.shared.global [%0], [%1], 16;" :: "r"(dst), "l"(src));
}
__device__ __forceinline__ void cp_commit() {
    asm volatile("cp.async.commit_group;" ::: "memory");
}
template<int N>
__device__ __forceinline__ void cp_wait() {
    asm volatile("cp.async.wait_group %0;" :: "n"(N) : "memory");
}
__device__ __forceinline__ float tf32r(float x) {
    uint32_t r;
    asm("cvt.rna.tf32.f32 %0, %1;" : "=r"(r) : "f"(x));
    return __uint_as_float(r);
}
__device__ __forceinline__ uint32_t ldsf(const float* p) {
    return *(const uint32_t*)p;
}
__device__ __forceinline__ void mma_tf32(float* c, const uint32_t* a,
                                         uint32_t b0, uint32_t b1) {
    asm volatile(
        "mma.sync.aligned.m16n8k8.row.col.f32.tf32.tf32.f32 "
        "{%0,%1,%2,%3}, {%4,%5,%6,%7}, {%8,%9}, {%0,%1,%2,%3};"
        : "+f"(c[0]), "+f"(c[1]), "+f"(c[2]), "+f"(c[3])
        : "r"(a[0]), "r"(a[1]), "r"(a[2]), "r"(a[3]), "r"(b0), "r"(b1));
}
__device__ __forceinline__ void bar_scan() {   // threads 0-127
    asm volatile("bar.sync 1, 128;" ::: "memory");
}
__device__ __forceinline__ void bar_work() {   // threads 128-383
    asm volatile("bar.sync 2, 256;" ::: "memory");
}

// ---------------- fused persistent kernel ----------------
constexpr int RNCTA = 128;
constexpr int FTPB  = 384;   // 128 scan + 256 worker threads

// head tile constants
constexpr int HSTRf   = 36;
constexpr int HTILEf  = 128 * HSTRf * 4;   // 18432 B
constexpr int HSTAGEf = HTILEf * 2;        // 36864 B
constexpr int HG_SMEM = HSTAGEf * 2;       // 73728 B dynamic worker smem

__global__ void __launch_bounds__(FTPB, 1) fused_kernel(
    const float* __restrict__ w_bb, const float* __restrict__ b_bb,
    const float* __restrict__ gamma, const float* __restrict__ beta,
    const float* __restrict__ w_out, const float* __restrict__ w_head,
    float* __restrict__ out)
{
    __shared__ float sV[Bb * Nn];          // 32 KB (scan)
    __shared__ float sRed[4][16][33];      // 8.4 KB (scan)
    extern __shared__ char wsm[];          // 73728 B (workers)

    const int tid = threadIdx.x;
    const int bid = blockIdx.x;

    if (tid < 128) {
        // ======================= SCAN (R9 logic, named barriers) =======================
        const int lane  = tid & 31;
        const int warp  = tid >> 5;
        const int jbase = bid * 8;
        const int j0    = jbase + warp * 2;

        float wreg[8][4][2];
#pragma unroll
        for (int i = 0; i < 8; i++) {
#pragma unroll
            for (int d = 0; d < 4; d++) {
                int k = 4 * lane + 128 * i + d;
                wreg[i][d][0] = w_bb[k * Nn + j0];
                wreg[i][d][1] = w_bb[k * Nn + j0 + 1];
            }
        }
        const float bias0 = b_bb[j0];
        const float bias1 = b_bb[j0 + 1];
        const uint32_t sV32 = smem_u32(sV);

        if (tid < 64) {
            int b = tid >> 3, c = tid & 7;
            g_S[0][b * Nn + jbase + c] = 0.f;
        }
        bar_scan();
        if (tid == 0) {
            unsigned my = g_gen;
            __threadfence();
            if (atomicAdd(&g_count, 1u) == RNCTA - 1) {
                g_count = 0u; __threadfence(); g_gen = my + 1u;
            } else { while (g_gen == my) { } }
        }
        bar_scan();

        int cur = 0;
#pragma unroll 1
        for (int t = 0; t < Tt; t++) {
#pragma unroll 1
            for (int step = 0; step < 4; step++) {
                const float4* src = (const float4*)&g_S[cur][0];
                float acc[16];
#pragma unroll
                for (int o = 0; o < 16; o++) acc[o] = 0.f;

                if (step == 0) {
                    const float4* xs = (const float4*)g_X;
                    for (int r = tid; r < (Bb * Nn) / 4; r += 128) {
                        float4 a = __ldcg(src + r);
                        int b  = r >> 8;
                        int k4 = r & 255;
                        float4 x = xs[(b * Tt + t) * (Nn / 4) + k4];
                        a.x += x.x; a.y += x.y; a.z += x.z; a.w += x.w;
                        ((float4*)sV)[r] = a;
                    }
                    bar_scan();
#pragma unroll
                    for (int i = 0; i < 8; i++) {
#pragma unroll
                        for (int b = 0; b < Bb; b++) {
                            float4 v = *(const float4*)&sV[b * Nn + 4 * lane + 128 * i];
                            acc[b*2+0] = fmaf(v.x, wreg[i][0][0], acc[b*2+0]);
                            acc[b*2+0] = fmaf(v.y, wreg[i][1][0], acc[b*2+0]);
                            acc[b*2+0] = fmaf(v.z, wreg[i][2][0], acc[b*2+0]);
                            acc[b*2+0] = fmaf(v.w, wreg[i][3][0], acc[b*2+0]);
                            acc[b*2+1] = fmaf(v.x, wreg[i][0][1], acc[b*2+1]);
                            acc[b*2+1] = fmaf(v.y, wreg[i][1][1], acc[b*2+1]);
                            acc[b*2+1] = fmaf(v.z, wreg[i][2][1], acc[b*2+1]);
                            acc[b*2+1] = fmaf(v.w, wreg[i][3][1], acc[b*2+1]);
                        }
                    }
                } else {
#pragma unroll
                    for (int k = 0; k < 8; k++) {
                        int r = tid + k * 128;
                        cp16(sV32 + r * 16, src + r);
                    }
                    cp_commit();
#pragma unroll
                    for (int k = 8; k < 16; k++) {
                        int r = tid + k * 128;
                        cp16(sV32 + r * 16, src + r);
                    }
                    cp_commit();

                    cp_wait<1>();
                    bar_scan();
#pragma unroll
                    for (int i = 0; i < 8; i++) {
#pragma unroll
                        for (int b = 0; b < 4; b++) {
                            float4 v = *(const float4*)&sV[b * Nn + 4 * lane + 128 * i];
                            acc[b*2+0] = fmaf(v.x, wreg[i][0][0], acc[b*2+0]);
                            acc[b*2+0] = fmaf(v.y, wreg[i][1][0], acc[b*2+0]);
                            acc[b*2+0] = fmaf(v.z, wreg[i][2][0], acc[b*2+0]);
                            acc[b*2+0] = fmaf(v.w, wreg[i][3][0], acc[b*2+0]);
                            acc[b*2+1] = fmaf(v.x, wreg[i][0][1], acc[b*2+1]);
                            acc[b*2+1] = fmaf(v.y, wreg[i][1][1], acc[b*2+1]);
                            acc[b*2+1] = fmaf(v.z, wreg[i][2][1], acc[b*2+1]);
                            acc[b*2+1] = fmaf(v.w, wreg[i][3][1], acc[b*2+1]);
                        }
                    }
                    cp_wait<0>();
                    bar_scan();
#pragma unroll
                    for (int i = 0; i < 8; i++) {
#pragma unroll
                        for (int b = 4; b < 8; b++) {
                            float4 v = *(const float4*)&sV[b * Nn + 4 * lane + 128 * i];
                            acc[b*2+0] = fmaf(v.x, wreg[i][0][0], acc[b*2+0]);
                            acc[b*2+0] = fmaf(v.y, wreg[i][1][0], acc[b*2+0]);
                            acc[b*2+0] = fmaf(v.z, wreg[i][2][0], acc[b*2+0]);
                            acc[b*2+0] = fmaf(v.w, wreg[i][3][0], acc[b*2+0]);
                            acc[b*2+1] = fmaf(v.x, wreg[i][0][1], acc[b*2+1]);
                            acc[b*2+1] = fmaf(v.y, wreg[i][1][1], acc[b*2+1]);
                            acc[b*2+1] = fmaf(v.z, wreg[i][2][1], acc[b*2+1]);
                            acc[b*2+1] = fmaf(v.w, wreg[i][3][1], acc[b*2+1]);
                        }
                    }
                }

#pragma unroll
                for (int o = 0; o < 16; o++) sRed[warp][o][lane] = acc[o];
                __syncwarp();

                const int nxt = cur ^ 1;
                {
                    const int o = lane >> 1;
                    const int h = lane & 1;
                    float s = 0.f;
#pragma unroll
                    for (int l = 0; l < 16; l++) s += sRed[warp][o][h * 16 + l];
                    s += __shfl_xor_sync(0xffffffffu, s, 1);
                    if (h == 0) {
                        int b = o >> 1, j = o & 1;
                        s += (j ? bias1 : bias0);
                        float sn = tanhf(s);
                        g_S[nxt][b * Nn + j0 + j] = sn;
                        if (step == 3) g_H[(t * Bb + b) * Nn + j0 + j] = sn;  // t-major
                    }
                }
                cur ^= 1;

                bar_scan();
                if (tid == 0) {
                    unsigned my = g_gen;
                    __threadfence();
                    if (atomicAdd(&g_count, 1u) == RNCTA - 1) {
                        g_count = 0u; __threadfence(); g_gen = my + 1u;
                    } else { while (g_gen == my) { } }
                }
                bar_scan();
            }
        }
    } else {
        // ======================= EPILOGUE WORKERS (256 threads) =======================
        const int wtid = tid - 128;
        const int lane = wtid & 31;
        const int warp = wtid >> 5;     // 0..7

        // --- Stage -1: transpose + tf32-round w_head into g_Bt (scan-chunk-0 idle time)
        {
            float (*tile)[33] = (float(*)[33])wsm;
            const int tx  = wtid & 31;
            const int ty8 = wtid >> 5;   // 0..7
#pragma unroll 1
            for (int ti = bid; ti < 24000; ti += RNCTA) {
                int n0 = (ti % 1000) * 32;
                int k0 = (ti / 1000) * 32;
#pragma unroll
                for (int j = 0; j < 32; j += 8)
                    tile[ty8 + j][tx] = w_head[(size_t)(k0 + ty8 + j) * Vv + n0 + tx];
                bar_work();
#pragma unroll
                for (int j = 0; j < 32; j += 8)
                    g_Bt[(size_t)(n0 + ty8 + j) * Ee + k0 + tx] = tf32r(tile[tx][ty8 + j]);
                bar_work();
            }
        }

#pragma unroll 1
        for (int c = 0; c < 4; c++) {
            // --- wait for scan chunk c (backoff poll: keep off the scan's hot line)
            if (tid == 128) {
                unsigned thr = 1u + 256u * (unsigned)(c + 1);
                while (g_gen < thr) { __nanosleep(256); }
            }
            bar_work();

            // --- Stage 1: layernorm, warp-per-row (no block barriers)
            if (warp < 4) {
                int row = c * RCH + bid * 4 + warp;
                const float4* srcv = (const float4*)(g_H + (size_t)row * Nn);
                float4 v[8];
                float s = 0.f, q = 0.f;
#pragma unroll
                for (int i = 0; i < 8; i++) {
                    v[i] = __ldcg(srcv + lane + i * 32);
                    s += v[i].x + v[i].y + v[i].z + v[i].w;
                    q += v[i].x*v[i].x + v[i].y*v[i].y + v[i].z*v[i].z + v[i].w*v[i].w;
                }
#pragma unroll
                for (int off = 16; off; off >>= 1) {
                    s += __shfl_xor_sync(0xffffffffu, s, off);
                    q += __shfl_xor_sync(0xffffffffu, q, off);
                }
                float m   = s * (1.f / Nn);
                float var = q * (1.f / Nn) - m * m;
                float r   = rsqrtf(var + 1e-5f);
#pragma unroll
                for (int i = 0; i < 8; i++) {
                    float4 g  = ((const float4*)gamma)[lane + i * 32];
                    float4 be = ((const float4*)beta)[lane + i * 32];
                    float4 o;
                    o.x = (v[i].x - m) * r * g.x + be.x;
                    o.y = (v[i].y - m) * r * g.y + be.y;
                    o.z = (v[i].z - m) * r * g.z + be.z;
                    o.w = (v[i].w - m) * r * g.w + be.w;
                    ((float4*)(g_Hn + (size_t)row * Nn))[lane + i * 32] = o;
                }
            }

            // --- worker grid barrier: all ln done
            bar_work();
            if (tid == 128) {
                unsigned my = g_wgen;
                __threadfence();
                if (atomicAdd(&g_wcount, 1u) == RNCTA - 1) {
                    g_wcount = 0u; __threadfence(); g_wgen = my + 1u;
                } else { while (g_wgen == my) { __nanosleep(128); } }
            }
            bar_work();

            // --- Stage 2: P_chunk = Hn_chunk @ w_out (tf32), 64x64 tiles on 96 CTAs
            if (bid < 96) {
                float* As = (float*)wsm;          // [8][64]
                float* Bs = As + 8 * 64;          // [8][64]
                const int mt = bid / 12, nt = bid % 12;
                const int bm = c * RCH + mt * 64;
                const int bn = nt * 64;
                const int arow = wtid >> 2;          // 0..63
                const int acol = (wtid & 3) * 2;     // 0,2,4,6
                const int brow = wtid >> 5;          // 0..7
                const int bcol = (wtid & 31) * 2;    // 0..62
                const int tr = wtid >> 4;            // 0..15
                const int tc = wtid & 15;

                float acc[4][4];
#pragma unroll
                for (int i = 0; i < 4; i++)
#pragma unroll
                    for (int j = 0; j < 4; j++) acc[i][j] = 0.f;

#pragma unroll 1
                for (int kb = 0; kb < Nn; kb += 8) {
                    float2 a = __ldcg((const float2*)(g_Hn + (size_t)(bm + arow) * Nn + kb + acol));
                    float2 b = *(const float2*)(w_out + (size_t)(kb + brow) * Ee + bn + bcol);
                    As[(acol + 0) * 64 + arow] = a.x;
                    As[(acol + 1) * 64 + arow] = a.y;
                    Bs[brow * 64 + bcol]     = b.x;
                    Bs[brow * 64 + bcol + 1] = b.y;
                    bar_work();
#pragma unroll
                    for (int k = 0; k < 8; k++) {
                        float rm[4], rn[4];
#pragma unroll
                        for (int i = 0; i < 4; i++) rm[i] = As[k * 64 + tr * 4 + i];
#pragma unroll
                        for (int j = 0; j < 4; j++) rn[j] = Bs[k * 64 + tc * 4 + j];
#pragma unroll
                        for (int i = 0; i < 4; i++)
#pragma unroll
                            for (int j = 0; j < 4; j++)
                                acc[i][j] = fmaf(rm[i], rn[j], acc[i][j]);
                    }
                    bar_work();
                }
#pragma unroll
                for (int i = 0; i < 4; i++) {
                    size_t crow = (size_t)(bm + tr * 4 + i) * Ee + bn + tc * 4;
                    float4 v;
                    v.x = tf32r(acc[i][0]); v.y = tf32r(acc[i][1]);
                    v.z = tf32r(acc[i][2]); v.w = tf32r(acc[i][3]);
                    *(float4*)(g_P + crow) = v;
                }
            }

            // --- worker grid barrier: P chunk ready (also guards Bt after chunk 0)
            bar_work();
            if (tid == 128) {
                unsigned my = g_wgen;
                __threadfence();
                if (atomicAdd(&g_wcount, 1u) == RNCTA - 1) {
                    g_wcount = 0u; __threadfence(); g_wgen = my + 1u;
                } else { while (g_wgen == my) { __nanosleep(128); } }
            }
            bar_work();

            // --- Stage 3: head GEMM for this chunk: 4 x 250 = 1000 tiles
            const uint32_t sbase = smem_u32(wsm);
#pragma unroll 1
            for (int ti = bid; ti < 1000; ti += RNCTA) {
                const int mt = ti / 250, nt = ti % 250;
                const int m0 = c * RCH + mt * 128;
                const int n0 = nt * 128;
                const int wm = (warp >> 1) * 32;
                const int wn = (warp & 1) * 64;
                const int gq = lane >> 2;
                const int tq = lane & 3;

                const int lr = wtid >> 1;
                const int lc = (wtid & 1) * 16;
                const uint32_t soff = (uint32_t)(lr * HSTRf + lc) * 4;
                const float* gA = g_P  + (size_t)(m0 + lr) * Ee + lc;
                const float* gB = g_Bt + (size_t)(n0 + lr) * Ee + lc;

                float cc[2][8][4];
#pragma unroll
                for (int i = 0; i < 2; i++)
#pragma unroll
                    for (int j = 0; j < 8; j++)
#pragma unroll
                        for (int q = 0; q < 4; q++) cc[i][j][q] = 0.f;

                {
                    uint32_t dA = sbase + soff;
                    uint32_t dB = sbase + HTILEf + soff;
#pragma unroll
                    for (int q = 0; q < 4; q++) {
                        cp16(dA + q * 16, gA + q * 4);
                        cp16(dB + q * 16, gB + q * 4);
                    }
                    cp_commit();
                }

#pragma unroll 1
                for (int it = 0; it < 24; it++) {
                    if (it + 1 < 24) {
                        const int st = (it + 1) & 1;
                        const int kb = (it + 1) * 32;
                        uint32_t dA = sbase + st * HSTAGEf + soff;
                        uint32_t dB = sbase + st * HSTAGEf + HTILEf + soff;
#pragma unroll
                        for (int q = 0; q < 4; q++) {
                            cp16(dA + q * 16, gA + kb + q * 4);
                            cp16(dB + q * 16, gB + kb + q * 4);
                        }
                        cp_commit();
                        cp_wait<1>();
                    } else {
                        cp_wait<0>();
                    }
                    bar_work();

                    const float* sA = (const float*)(wsm + (it & 1) * HSTAGEf);
                    const float* sB = (const float*)(wsm + (it & 1) * HSTAGEf + HTILEf);

#pragma unroll
                    for (int ks = 0; ks < 4; ks++) {
                        const int k0 = ks * 8;
                        uint32_t a[2][4];
#pragma unroll
                        for (int i = 0; i < 2; i++) {
                            const float* r0 = &sA[(wm + 16 * i + gq) * HSTRf + k0 + tq];
                            const float* r1 = &sA[(wm + 16 * i + gq + 8) * HSTRf + k0 + tq];
                            a[i][0] = ldsf(r0);
                            a[i][1] = ldsf(r1);
                            a[i][2] = ldsf(r0 + 4);
                            a[i][3] = ldsf(r1 + 4);
                        }
#pragma unroll
                        for (int j = 0; j < 8; j++) {
                            const float* nb = &sB[(wn + 8 * j + gq) * HSTRf + k0 + tq];
                            uint32_t b0 = ldsf(nb);
                            uint32_t b1 = ldsf(nb + 4);
                            mma_tf32(cc[0][j], a[0], b0, b1);
                            mma_tf32(cc[1][j], a[1], b0, b1);
                        }
                    }
                    bar_work();
                }

                // epilogue: remap t-major row -> output row (b*Tt + t)
#pragma unroll
                for (int i = 0; i < 2; i++) {
#pragma unroll
                    for (int j = 0; j < 8; j++) {
                        int gr0 = m0 + wm + 16 * i + gq;
                        int gr1 = gr0 + 8;
                        int or0 = (gr0 & 7) * Tt + (gr0 >> 3);
                        int or1 = (gr1 & 7) * Tt + (gr1 >> 3);
                        int col = n0 + wn + 8 * j + 2 * tq;
                        float2 v0 = make_float2(cc[i][j][0], cc[i][j][1]);
                        float2 v1 = make_float2(cc[i][j][2], cc[i][j][3]);
                        *(float2*)(out + (size_t)or0 * Vv + col) = v0;
                        *(float2*)(out + (size_t)or1 * Vv + col) = v1;
                    }
                }
            }
        }
    }
}

// ---------------- prologue GEMM: X = emb[ids] @ w_in + b_in ----------------
__global__ void __launch_bounds__(256) sgemmA_kernel(
    const float* __restrict__ A, const float* __restrict__ Bm, float* __restrict__ C,
    const int* __restrict__ ids, const float* __restrict__ bias)
{
    constexpr int BM = 128, BN = 128, BK = 8;
    constexpr int N = Nn, K = Ee;
    __shared__ float As[BK][BM];
    __shared__ float Bs[BK][BN];

    const int tid = threadIdx.x;
    const int bm  = blockIdx.y * BM;
    const int bn  = blockIdx.x * BN;

    const int innerRowA = tid >> 1;
    const int innerColA = (tid & 1) * 4;
    const int innerRowB = tid >> 5;
    const int innerColB = (tid & 31) * 4;
    const int tr = tid >> 4;
    const int tc = tid & 15;

    const int arow = bm + innerRowA;
    const int arowBase = ids[arow] * K;

    float acc[8][8];
#pragma unroll
    for (int i = 0; i < 8; i++)
#pragma unroll
        for (int j = 0; j < 8; j++) acc[i][j] = 0.f;

    for (int kb = 0; kb < K; kb += BK) {
        float4 a = *(const float4*)(A + arowBase + kb + innerColA);
        float4 b = *(const float4*)(Bm + (kb + innerRowB) * N + bn + innerColB);
        As[innerColA + 0][innerRowA] = a.x;
        As[innerColA + 1][innerRowA] = a.y;
        As[innerColA + 2][innerRowA] = a.z;
        As[innerColA + 3][innerRowA] = a.w;
        *(float4*)&Bs[innerRowB][innerColB] = b;
        __syncthreads();

#pragma unroll
        for (int k = 0; k < BK; k++) {
            float rm[8], rn[8];
#pragma unroll
            for (int i = 0; i < 8; i++) rm[i] = As[k][tr * 8 + i];
#pragma unroll
            for (int j = 0; j < 8; j++) rn[j] = Bs[k][tc * 8 + j];
#pragma unroll
            for (int i = 0; i < 8; i++)
#pragma unroll
                for (int j = 0; j < 8; j++)
                    acc[i][j] = fmaf(rm[i], rn[j], acc[i][j]);
        }
        __syncthreads();
    }

#pragma unroll
    for (int i = 0; i < 8; i++) {
        int crow = (bm + tr * 8 + i) * N + bn + tc * 8;
#pragma unroll
        for (int j4 = 0; j4 < 2; j4++) {
            float4 v;
            v.x = acc[i][j4*4+0]; v.y = acc[i][j4*4+1];
            v.z = acc[i][j4*4+2]; v.w = acc[i][j4*4+3];
            float4 bb = *(const float4*)(bias + bn + tc * 8 + j4 * 4);
            v.x += bb.x; v.y += bb.y; v.z += bb.z; v.w += bb.w;
            *(float4*)(C + crow + j4 * 4) = v;
        }
    }
}

// ---------------- launch ----------------
extern "C" void kernel_launch(void* const* d_in, const int* in_sizes, int n_in,
                              void* d_out, int out_size)
{
    const int*   ids    = (const int*)  d_in[0];
    const float* emb    = (const float*)d_in[1];
    const float* w_in   = (const float*)d_in[2];
    const float* b_in   = (const float*)d_in[3];
    const float* w_bb   = (const float*)d_in[4];
    const float* b_bb   = (const float*)d_in[5];
    const float* gamma  = (const float*)d_in[6];
    const float* beta   = (const float*)d_in[7];
    const float* w_out  = (const float*)d_in[8];
    const float* w_head = (const float*)d_in[9];
    float* out = (float*)d_out;

    float* pX = nullptr;
    cudaGetSymbolAddress((void**)&pX, g_X);

    cudaFuncSetAttribute(fused_kernel,
                         cudaFuncAttributeMaxDynamicSharedMemorySize, HG_SMEM);

    // 0. reset barrier state
    init_barrier_kernel<<<1, 1>>>();

    // 1. X = emb[ids] @ w_in + b_in
    {
        dim3 g(Nn / 128, BT / 128);
        sgemmA_kernel<<<g, 256>>>(emb, w_in, pX, ids, b_in);
    }

    // 2. fused scan + warp-specialized epilogue pipeline (writes out directly)
    fused_kernel<<<RNCTA, FTPB, HG_SMEM>>>(w_bb, b_bb, gamma, beta, w_out, w_head, out);
}

// round 17
// speedup vs baseline: 1.0452x; 1.0015x over previous
#include <cuda_runtime.h>
#include <math.h>
#include <stdint.h>

// Problem constants
constexpr int Bb  = 8;
constexpr int Tt  = 256;
constexpr int Ee  = 768;
constexpr int Nn  = 1024;
constexpr int Vv  = 32000;
constexpr int BT  = Bb * Tt;   // 2048
constexpr int TCH = 32;        // timesteps per chunk (8 chunks)
constexpr int NCH = Tt / TCH;  // 8
constexpr int RCH = TCH * Bb;  // 256 rows per chunk (t-major)

// ---------------- device scratch ----------------
__device__ float g_X [BT * Nn];
__device__ float g_S [2][Bb * Nn];
__device__ float g_H [BT * Nn];          // t-major: row = t*Bb + b
__device__ float g_Hn[BT * Nn];          // t-major
__device__ float g_P [BT * Ee];          // t-major, tf32-rounded
__device__ float g_Bt[(size_t)Vv * Ee];  // w_head^T [V][E], tf32-rounded
__device__ unsigned g_count;
__device__ volatile unsigned g_gen;      // scan generation: 1 + substeps done
__device__ unsigned g_wcount;
__device__ volatile unsigned g_wgen;     // worker stage barrier

__global__ void init_barrier_kernel() {
    g_count = 0u; g_gen = 0u;
    g_wcount = 0u; g_wgen = 0u;
}

// ---------------- helpers ----------------
__device__ __forceinline__ uint32_t smem_u32(const void* p) {
    uint32_t a;
    asm("{ .reg .u64 t; cvta.to.shared.u64 t, %1; cvt.u32.u64 %0, t; }" : "=r"(a) : "l"(p));
    return a;
}
__device__ __forceinline__ void cp16(uint32_t dst, const void* src) {
    asm volatile("cp.async.cg.shared.global [%0], [%1], 16;" :: "r"(dst), "l"(src));
}
__device__ __forceinline__ void cp_commit() {
    asm volatile("cp.async.commit_group;" ::: "memory");
}
template<int N>
__device__ __forceinline__ void cp_wait() {
    asm volatile("cp.async.wait_group %0;" :: "n"(N) : "memory");
}
__device__ __forceinline__ float tf32r(float x) {
    uint32_t r;
    asm("cvt.rna.tf32.f32 %0, %1;" : "=r"(r) : "f"(x));
    return __uint_as_float(r);
}
__device__ __forceinline__ uint32_t ldsf(const float* p) {
    return *(const uint32_t*)p;
}
__device__ __forceinline__ void mma_tf32(float* c, const uint32_t* a,
                                         uint32_t b0, uint32_t b1) {
    asm volatile(
        "mma.sync.aligned.m16n8k8.row.col.f32.tf32.tf32.f32 "
        "{%0,%1,%2,%3}, {%4,%5,%6,%7}, {%8,%9}, {%0,%1,%2,%3};"
        : "+f"(c[0]), "+f"(c[1]), "+f"(c[2]), "+f"(c[3])
        : "r"(a[0]), "r"(a[1]), "r"(a[2]), "r"(a[3]), "r"(b0), "r"(b1));
}
__device__ __forceinline__ void bar_scan() {   // threads 0-127
    asm volatile("bar.sync 1, 128;" ::: "memory");
}
__device__ __forceinline__ void bar_work() {   // threads 128-383
    asm volatile("bar.sync 2, 256;" ::: "memory");
}

// ---------------- fused persistent kernel ----------------
constexpr int RNCTA = 128;
constexpr int FTPB  = 384;   // 128 scan + 256 worker threads

// head tile constants
constexpr int HSTRf   = 36;
constexpr int HTILEf  = 128 * HSTRf * 4;   // 18432 B
constexpr int HSTAGEf = HTILEf * 2;        // 36864 B
constexpr int HG_SMEM = HSTAGEf * 2;       // 73728 B dynamic worker smem

__global__ void __launch_bounds__(FTPB, 1) fused_kernel(
    const float* __restrict__ w_bb, const float* __restrict__ b_bb,
    const float* __restrict__ gamma, const float* __restrict__ beta,
    const float* __restrict__ w_out, const float* __restrict__ w_head,
    float* __restrict__ out)
{
    __shared__ float sV[Bb * Nn];          // 32 KB (scan)
    __shared__ float sRed[4][16][33];      // 8.4 KB (scan)
    extern __shared__ char wsm[];          // 73728 B (workers)

    const int tid = threadIdx.x;
    const int bid = blockIdx.x;

    if (tid < 128) {
        // ======================= SCAN (R9 logic, named barriers) =======================
        const int lane  = tid & 31;
        const int warp  = tid >> 5;
        const int jbase = bid * 8;
        const int j0    = jbase + warp * 2;

        float wreg[8][4][2];
#pragma unroll
        for (int i = 0; i < 8; i++) {
#pragma unroll
            for (int d = 0; d < 4; d++) {
                int k = 4 * lane + 128 * i + d;
                wreg[i][d][0] = w_bb[k * Nn + j0];
                wreg[i][d][1] = w_bb[k * Nn + j0 + 1];
            }
        }
        const float bias0 = b_bb[j0];
        const float bias1 = b_bb[j0 + 1];
        const uint32_t sV32 = smem_u32(sV);

        if (tid < 64) {
            int b = tid >> 3, c = tid & 7;
            g_S[0][b * Nn + jbase + c] = 0.f;
        }
        bar_scan();
        if (tid == 0) {
            unsigned my = g_gen;
            __threadfence();
            if (atomicAdd(&g_count, 1u) == RNCTA - 1) {
                g_count = 0u; __threadfence(); g_gen = my + 1u;
            } else { while (g_gen == my) { } }
        }
        bar_scan();

        int cur = 0;
#pragma unroll 1
        for (int t = 0; t < Tt; t++) {
#pragma unroll 1
            for (int step = 0; step < 4; step++) {
                const float4* src = (const float4*)&g_S[cur][0];
                float acc[16];
#pragma unroll
                for (int o = 0; o < 16; o++) acc[o] = 0.f;

                if (step == 0) {
                    const float4* xs = (const float4*)g_X;
                    for (int r = tid; r < (Bb * Nn) / 4; r += 128) {
                        float4 a = __ldcg(src + r);
                        int b  = r >> 8;
                        int k4 = r & 255;
                        float4 x = xs[(b * Tt + t) * (Nn / 4) + k4];
                        a.x += x.x; a.y += x.y; a.z += x.z; a.w += x.w;
                        ((float4*)sV)[r] = a;
                    }
                    bar_scan();
#pragma unroll
                    for (int i = 0; i < 8; i++) {
#pragma unroll
                        for (int b = 0; b < Bb; b++) {
                            float4 v = *(const float4*)&sV[b * Nn + 4 * lane + 128 * i];
                            acc[b*2+0] = fmaf(v.x, wreg[i][0][0], acc[b*2+0]);
                            acc[b*2+0] = fmaf(v.y, wreg[i][1][0], acc[b*2+0]);
                            acc[b*2+0] = fmaf(v.z, wreg[i][2][0], acc[b*2+0]);
                            acc[b*2+0] = fmaf(v.w, wreg[i][3][0], acc[b*2+0]);
                            acc[b*2+1] = fmaf(v.x, wreg[i][0][1], acc[b*2+1]);
                            acc[b*2+1] = fmaf(v.y, wreg[i][1][1], acc[b*2+1]);
                            acc[b*2+1] = fmaf(v.z, wreg[i][2][1], acc[b*2+1]);
                            acc[b*2+1] = fmaf(v.w, wreg[i][3][1], acc[b*2+1]);
                        }
                    }
                } else {
#pragma unroll
                    for (int k = 0; k < 8; k++) {
                        int r = tid + k * 128;
                        cp16(sV32 + r * 16, src + r);
                    }
                    cp_commit();
#pragma unroll
                    for (int k = 8; k < 16; k++) {
                        int r = tid + k * 128;
                        cp16(sV32 + r * 16, src + r);
                    }
                    cp_commit();

                    cp_wait<1>();
                    bar_scan();
#pragma unroll
                    for (int i = 0; i < 8; i++) {
#pragma unroll
                        for (int b = 0; b < 4; b++) {
                            float4 v = *(const float4*)&sV[b * Nn + 4 * lane + 128 * i];
                            acc[b*2+0] = fmaf(v.x, wreg[i][0][0], acc[b*2+0]);
                            acc[b*2+0] = fmaf(v.y, wreg[i][1][0], acc[b*2+0]);
                            acc[b*2+0] = fmaf(v.z, wreg[i][2][0], acc[b*2+0]);
                            acc[b*2+0] = fmaf(v.w, wreg[i][3][0], acc[b*2+0]);
                            acc[b*2+1] = fmaf(v.x, wreg[i][0][1], acc[b*2+1]);
                            acc[b*2+1] = fmaf(v.y, wreg[i][1][1], acc[b*2+1]);
                            acc[b*2+1] = fmaf(v.z, wreg[i][2][1], acc[b*2+1]);
                            acc[b*2+1] = fmaf(v.w, wreg[i][3][1], acc[b*2+1]);
                        }
                    }
                    cp_wait<0>();
                    bar_scan();
#pragma unroll
                    for (int i = 0; i < 8; i++) {
#pragma unroll
                        for (int b = 4; b < 8; b++) {
                            float4 v = *(const float4*)&sV[b * Nn + 4 * lane + 128 * i];
                            acc[b*2+0] = fmaf(v.x, wreg[i][0][0], acc[b*2+0]);
                            acc[b*2+0] = fmaf(v.y, wreg[i][1][0], acc[b*2+0]);
                            acc[b*2+0] = fmaf(v.z, wreg[i][2][0], acc[b*2+0]);
                            acc[b*2+0] = fmaf(v.w, wreg[i][3][0], acc[b*2+0]);
                            acc[b*2+1] = fmaf(v.x, wreg[i][0][1], acc[b*2+1]);
                            acc[b*2+1] = fmaf(v.y, wreg[i][1][1], acc[b*2+1]);
                            acc[b*2+1] = fmaf(v.z, wreg[i][2][1], acc[b*2+1]);
                            acc[b*2+1] = fmaf(v.w, wreg[i][3][1], acc[b*2+1]);
                        }
                    }
                }

#pragma unroll
                for (int o = 0; o < 16; o++) sRed[warp][o][lane] = acc[o];
                __syncwarp();

                const int nxt = cur ^ 1;
                {
                    const int o = lane >> 1;
                    const int h = lane & 1;
                    float s = 0.f;
#pragma unroll
                    for (int l = 0; l < 16; l++) s += sRed[warp][o][h * 16 + l];
                    s += __shfl_xor_sync(0xffffffffu, s, 1);
                    if (h == 0) {
                        int b = o >> 1, j = o & 1;
                        s += (j ? bias1 : bias0);
                        float sn = tanhf(s);
                        g_S[nxt][b * Nn + j0 + j] = sn;
                        if (step == 3) g_H[(t * Bb + b) * Nn + j0 + j] = sn;  // t-major
                    }
                }
                cur ^= 1;

                bar_scan();
                if (tid == 0) {
                    unsigned my = g_gen;
                    __threadfence();
                    if (atomicAdd(&g_count, 1u) == RNCTA - 1) {
                        g_count = 0u; __threadfence(); g_gen = my + 1u;
                    } else { while (g_gen == my) { } }
                }
                bar_scan();
            }
        }
    } else {
        // ======================= EPILOGUE WORKERS (256 threads) =======================
        const int wtid = tid - 128;
        const int lane = wtid & 31;
        const int warp = wtid >> 5;     // 0..7

        // --- Stage -1: transpose + tf32-round w_head into g_Bt (scan-chunk-0 idle time)
        {
            float (*tile)[33] = (float(*)[33])wsm;
            const int tx  = wtid & 31;
            const int ty8 = wtid >> 5;   // 0..7
#pragma unroll 1
            for (int ti = bid; ti < 24000; ti += RNCTA) {
                int n0 = (ti % 1000) * 32;
                int k0 = (ti / 1000) * 32;
#pragma unroll
                for (int j = 0; j < 32; j += 8)
                    tile[ty8 + j][tx] = w_head[(size_t)(k0 + ty8 + j) * Vv + n0 + tx];
                bar_work();
#pragma unroll
                for (int j = 0; j < 32; j += 8)
                    g_Bt[(size_t)(n0 + ty8 + j) * Ee + k0 + tx] = tf32r(tile[tx][ty8 + j]);
                bar_work();
            }
        }

#pragma unroll 1
        for (int c = 0; c < NCH; c++) {
            // --- wait for scan chunk c (backoff poll: keep off the scan's hot line)
            if (tid == 128) {
                unsigned thr = 1u + (unsigned)(TCH * 4) * (unsigned)(c + 1);
                while (g_gen < thr) { __nanosleep(256); }
            }
            bar_work();

            // --- Stage 1: layernorm, warp-per-row (256 rows/chunk => warp<2)
            if (warp < 2) {
                int row = c * RCH + bid * 2 + warp;
                const float4* srcv = (const float4*)(g_H + (size_t)row * Nn);
                float4 v[8];
                float s = 0.f, q = 0.f;
#pragma unroll
                for (int i = 0; i < 8; i++) {
                    v[i] = __ldcg(srcv + lane + i * 32);
                    s += v[i].x + v[i].y + v[i].z + v[i].w;
                    q += v[i].x*v[i].x + v[i].y*v[i].y + v[i].z*v[i].z + v[i].w*v[i].w;
                }
#pragma unroll
                for (int off = 16; off; off >>= 1) {
                    s += __shfl_xor_sync(0xffffffffu, s, off);
                    q += __shfl_xor_sync(0xffffffffu, q, off);
                }
                float m   = s * (1.f / Nn);
                float var = q * (1.f / Nn) - m * m;
                float r   = rsqrtf(var + 1e-5f);
#pragma unroll
                for (int i = 0; i < 8; i++) {
                    float4 g  = ((const float4*)gamma)[lane + i * 32];
                    float4 be = ((const float4*)beta)[lane + i * 32];
                    float4 o;
                    o.x = (v[i].x - m) * r * g.x + be.x;
                    o.y = (v[i].y - m) * r * g.y + be.y;
                    o.z = (v[i].z - m) * r * g.z + be.z;
                    o.w = (v[i].w - m) * r * g.w + be.w;
                    ((float4*)(g_Hn + (size_t)row * Nn))[lane + i * 32] = o;
                }
            }

            // --- worker grid barrier: all ln done
            bar_work();
            if (tid == 128) {
                unsigned my = g_wgen;
                __threadfence();
                if (atomicAdd(&g_wcount, 1u) == RNCTA - 1) {
                    g_wcount = 0u; __threadfence(); g_wgen = my + 1u;
                } else { while (g_wgen == my) { __nanosleep(128); } }
            }
            bar_work();

            // --- Stage 2: P_chunk = Hn_chunk @ w_out (tf32), 64x64 tiles on 48 CTAs
            if (bid < 48) {
                float* As = (float*)wsm;          // [8][64]
                float* Bs = As + 8 * 64;          // [8][64]
                const int mt = bid / 12, nt = bid % 12;
                const int bm = c * RCH + mt * 64;
                const int bn = nt * 64;
                const int arow = wtid >> 2;
                const int acol = (wtid & 3) * 2;
                const int brow = wtid >> 5;
                const int bcol = (wtid & 31) * 2;
                const int tr = wtid >> 4;
                const int tc = wtid & 15;

                float acc[4][4];
#pragma unroll
                for (int i = 0; i < 4; i++)
#pragma unroll
                    for (int j = 0; j < 4; j++) acc[i][j] = 0.f;

#pragma unroll 1
                for (int kb = 0; kb < Nn; kb += 8) {
                    float2 a = __ldcg((const float2*)(g_Hn + (size_t)(bm + arow) * Nn + kb + acol));
                    float2 b = *(const float2*)(w_out + (size_t)(kb + brow) * Ee + bn + bcol);
                    As[(acol + 0) * 64 + arow] = a.x;
                    As[(acol + 1) * 64 + arow] = a.y;
                    Bs[brow * 64 + bcol]     = b.x;
                    Bs[brow * 64 + bcol + 1] = b.y;
                    bar_work();
#pragma unroll
                    for (int k = 0; k < 8; k++) {
                        float rm[4], rn[4];
#pragma unroll
                        for (int i = 0; i < 4; i++) rm[i] = As[k * 64 + tr * 4 + i];
#pragma unroll
                        for (int j = 0; j < 4; j++) rn[j] = Bs[k * 64 + tc * 4 + j];
#pragma unroll
                        for (int i = 0; i < 4; i++)
#pragma unroll
                            for (int j = 0; j < 4; j++)
                                acc[i][j] = fmaf(rm[i], rn[j], acc[i][j]);
                    }
                    bar_work();
                }
#pragma unroll
                for (int i = 0; i < 4; i++) {
                    size_t crow = (size_t)(bm + tr * 4 + i) * Ee + bn + tc * 4;
                    float4 v;
                    v.x = tf32r(acc[i][0]); v.y = tf32r(acc[i][1]);
                    v.z = tf32r(acc[i][2]); v.w = tf32r(acc[i][3]);
                    *(float4*)(g_P + crow) = v;
                }
            }

            // --- worker grid barrier: P chunk ready (also guards Bt after chunk 0)
            bar_work();
            if (tid == 128) {
                unsigned my = g_wgen;
                __threadfence();
                if (atomicAdd(&g_wcount, 1u) == RNCTA - 1) {
                    g_wcount = 0u; __threadfence(); g_wgen = my + 1u;
                } else { while (g_wgen == my) { __nanosleep(128); } }
            }
            bar_work();

            // --- Stage 3: head GEMM for this chunk: 2 x 250 = 500 tiles
            const uint32_t sbase = smem_u32(wsm);
#pragma unroll 1
            for (int ti = bid; ti < 500; ti += RNCTA) {
                const int mt = ti / 250, nt = ti % 250;
                const int m0 = c * RCH + mt * 128;
                const int n0 = nt * 128;
                const int wm = (warp >> 1) * 32;
                const int wn = (warp & 1) * 64;
                const int gq = lane >> 2;
                const int tq = lane & 3;

                const int lr = wtid >> 1;
                const int lc = (wtid & 1) * 16;
                const uint32_t soff = (uint32_t)(lr * HSTRf + lc) * 4;
                const float* gA = g_P  + (size_t)(m0 + lr) * Ee + lc;
                const float* gB = g_Bt + (size_t)(n0 + lr) * Ee + lc;

                float cc[2][8][4];
#pragma unroll
                for (int i = 0; i < 2; i++)
#pragma unroll
                    for (int j = 0; j < 8; j++)
#pragma unroll
                        for (int q = 0; q < 4; q++) cc[i][j][q] = 0.f;

                {
                    uint32_t dA = sbase + soff;
                    uint32_t dB = sbase + HTILEf + soff;
#pragma unroll
                    for (int q = 0; q < 4; q++) {
                        cp16(dA + q * 16, gA + q * 4);
                        cp16(dB + q * 16, gB + q * 4);
                    }
                    cp_commit();
                }

#pragma unroll 1
                for (int it = 0; it < 24; it++) {
                    if (it + 1 < 24) {
                        const int st = (it + 1) & 1;
                        const int kb = (it + 1) * 32;
                        uint32_t dA = sbase + st * HSTAGEf + soff;
                        uint32_t dB = sbase + st * HSTAGEf + HTILEf + soff;
#pragma unroll
                        for (int q = 0; q < 4; q++) {
                            cp16(dA + q * 16, gA + kb + q * 4);
                            cp16(dB + q * 16, gB + kb + q * 4);
                        }
                        cp_commit();
                        cp_wait<1>();
                    } else {
                        cp_wait<0>();
                    }
                    bar_work();

                    const float* sA = (const float*)(wsm + (it & 1) * HSTAGEf);
                    const float* sB = (const float*)(wsm + (it & 1) * HSTAGEf + HTILEf);

#pragma unroll
                    for (int ks = 0; ks < 4; ks++) {
                        const int k0 = ks * 8;
                        uint32_t a[2][4];
#pragma unroll
                        for (int i = 0; i < 2; i++) {
                            const float* r0 = &sA[(wm + 16 * i + gq) * HSTRf + k0 + tq];
                            const float* r1 = &sA[(wm + 16 * i + gq + 8) * HSTRf + k0 + tq];
                            a[i][0] = ldsf(r0);
                            a[i][1] = ldsf(r1);
                            a[i][2] = ldsf(r0 + 4);
                            a[i][3] = ldsf(r1 + 4);
                        }
#pragma unroll
                        for (int j = 0; j < 8; j++) {
                            const float* nb = &sB[(wn + 8 * j + gq) * HSTRf + k0 + tq];
                            uint32_t b0 = ldsf(nb);
                            uint32_t b1 = ldsf(nb + 4);
                            mma_tf32(cc[0][j], a[0], b0, b1);
                            mma_tf32(cc[1][j], a[1], b0, b1);
                        }
                    }
                    bar_work();
                }

                // epilogue: remap t-major row -> output row (b*Tt + t)
#pragma unroll
                for (int i = 0; i < 2; i++) {
#pragma unroll
                    for (int j = 0; j < 8; j++) {
                        int gr0 = m0 + wm + 16 * i + gq;
                        int gr1 = gr0 + 8;
                        int or0 = (gr0 & 7) * Tt + (gr0 >> 3);
                        int or1 = (gr1 & 7) * Tt + (gr1 >> 3);
                        int col = n0 + wn + 8 * j + 2 * tq;
                        float2 v0 = make_float2(cc[i][j][0], cc[i][j][1]);
                        float2 v1 = make_float2(cc[i][j][2], cc[i][j][3]);
                        *(float2*)(out + (size_t)or0 * Vv + col) = v0;
                        *(float2*)(out + (size_t)or1 * Vv + col) = v1;
                    }
                }
            }
        }
    }
}

// ---------------- prologue GEMM: X = emb[ids] @ w_in + b_in ----------------
__global__ void __launch_bounds__(256) sgemmA_kernel(
    const float* __restrict__ A, const float* __restrict__ Bm, float* __restrict__ C,
    const int* __restrict__ ids, const float* __restrict__ bias)
{
    constexpr int BM = 128, BN = 128, BK = 8;
    constexpr int N = Nn, K = Ee;
    __shared__ float As[BK][BM];
    __shared__ float Bs[BK][BN];

    const int tid = threadIdx.x;
    const int bm  = blockIdx.y * BM;
    const int bn  = blockIdx.x * BN;

    const int innerRowA = tid >> 1;
    const int innerColA = (tid & 1) * 4;
    const int innerRowB = tid >> 5;
    const int innerColB = (tid & 31) * 4;
    const int tr = tid >> 4;
    const int tc = tid & 15;

    const int arow = bm + innerRowA;
    const int arowBase = ids[arow] * K;

    float acc[8][8];
#pragma unroll
    for (int i = 0; i < 8; i++)
#pragma unroll
        for (int j = 0; j < 8; j++) acc[i][j] = 0.f;

    for (int kb = 0; kb < K; kb += BK) {
        float4 a = *(const float4*)(A + arowBase + kb + innerColA);
        float4 b = *(const float4*)(Bm + (kb + innerRowB) * N + bn + innerColB);
        As[innerColA + 0][innerRowA] = a.x;
        As[innerColA + 1][innerRowA] = a.y;
        As[innerColA + 2][innerRowA] = a.z;
        As[innerColA + 3][innerRowA] = a.w;
        *(float4*)&Bs[innerRowB][innerColB] = b;
        __syncthreads();

#pragma unroll
        for (int k = 0; k < BK; k++) {
            float rm[8], rn[8];
#pragma unroll
            for (int i = 0; i < 8; i++) rm[i] = As[k][tr * 8 + i];
#pragma unroll
            for (int j = 0; j < 8; j++) rn[j] = Bs[k][tc * 8 + j];
#pragma unroll
            for (int i = 0; i < 8; i++)
#pragma unroll
                for (int j = 0; j < 8; j++)
                    acc[i][j] = fmaf(rm[i], rn[j], acc[i][j]);
        }
        __syncthreads();
    }

#pragma unroll
    for (int i = 0; i < 8; i++) {
        int crow = (bm + tr * 8 + i) * N + bn + tc * 8;
#pragma unroll
        for (int j4 = 0; j4 < 2; j4++) {
            float4 v;
            v.x = acc[i][j4*4+0]; v.y = acc[i][j4*4+1];
            v.z = acc[i][j4*4+2]; v.w = acc[i][j4*4+3];
            float4 bb = *(const float4*)(bias + bn + tc * 8 + j4 * 4);
            v.x += bb.x; v.y += bb.y; v.z += bb.z; v.w += bb.w;
            *(float4*)(C + crow + j4 * 4) = v;
        }
    }
}

// ---------------- launch ----------------
extern "C" void kernel_launch(void* const* d_in, const int* in_sizes, int n_in,
                              void* d_out, int out_size)
{
    const int*   ids    = (const int*)  d_in[0];
    const float* emb    = (const float*)d_in[1];
    const float* w_in   = (const float*)d_in[2];
    const float* b_in   = (const float*)d_in[3];
    const float* w_bb   = (const float*)d_in[4];
    const float* b_bb   = (const float*)d_in[5];
    const float* gamma  = (const float*)d_in[6];
    const float* beta   = (const float*)d_in[7];
    const float* w_out  = (const float*)d_in[8];
    const float* w_head = (const float*)d_in[9];
    float* out = (float*)d_out;

    float* pX = nullptr;
    cudaGetSymbolAddress((void**)&pX, g_X);

    cudaFuncSetAttribute(fused_kernel,
                         cudaFuncAttributeMaxDynamicSharedMemorySize, HG_SMEM);

    // 0. reset barrier state
    init_barrier_kernel<<<1, 1>>>();

    // 1. X = emb[ids] @ w_in + b_in
    {
        dim3 g(Nn / 128, BT / 128);
        sgemmA_kernel<<<g, 256>>>(emb, w_in, pX, ids, b_in);
    }

    // 2. fused scan + warp-specialized epilogue pipeline (writes out directly)
    fused_kernel<<<RNCTA, FTPB, HG_SMEM>>>(w_bb, b_bb, gamma, beta, w_out, w_head, out);
}